// round 3
// baseline (speedup 1.0000x reference)
#include <cuda_runtime.h>
#include <mma.h>
#include <math.h>

using namespace nvcuda;

// Problem constants
#define BB 256
#define TT 30
#define ML 31
#define VV 10000
#define HH 512
#define G4 2048            // 4*H
#define NROWS 7680         // TT*BB
#define BK 32
#define LDA 36             // shared lda (32 + 4 pad) -> 144B rows (16B aligned)
#define LDC 132            // shared C ld (128 + 4 pad)
#define BUFO (128 * LDA)   // floats per stage buffer
#define DSMEM_BYTES (4 * BUFO * 4)   // 73728 B: As[2] + Bs[2]; Cs reuses
#define NBLK 32            // persistent-step grid size

// ---------------- device scratch ----------------
__device__ int   g_order[BB];
__device__ int   g_declen[BB];
__device__ int   g_cnt[TT];
__device__ float g_gp[BB * G4];
__device__ float g_xp[(size_t)NROWS * G4];       // gp + xp + biases (pre-folded)
__device__ float g_hbuf[2][BB * HH];
__device__ float g_cc[BB * HH];
__device__ float g_hall[(size_t)NROWS * HH];
__device__ float g_rowsum[NROWS];
__device__ int   g_barcnt;
__device__ int   g_barflag;

typedef wmma::fragment<wmma::matrix_a, 16, 16, 8, wmma::precision::tf32, wmma::row_major> FragA;
typedef wmma::fragment<wmma::matrix_b, 16, 16, 8, wmma::precision::tf32, wmma::col_major> FragB;
typedef wmma::fragment<wmma::accumulator, 16, 16, 8, float> FragC;

__device__ __forceinline__ void cvtA(FragA& f) {
    #pragma unroll
    for (int q = 0; q < f.num_elements; q++) f.x[q] = wmma::__float_to_tf32(f.x[q]);
}
__device__ __forceinline__ void cvtB(FragB& f) {
    #pragma unroll
    for (int q = 0; q < f.num_elements; q++) f.x[q] = wmma::__float_to_tf32(f.x[q]);
}

__device__ __forceinline__ void cp16(float* s, const float* g) {
    unsigned d = (unsigned)__cvta_generic_to_shared(s);
    asm volatile("cp.async.cg.shared.global [%0], [%1], 16;" :: "r"(d), "l"(g));
}

// ---- common pipelined GEMM: C[128x128] += A[128x512] * B[128x512]^T ----
// arow/brow: this thread's staged row base (row = tid>>1), K-contiguous.
__device__ __forceinline__ void gemm_k512(const float* arow, const float* brow,
                                          float* As, float* Bs,
                                          FragC (&c)[2][4], int tid) {
    int wp = tid >> 5, wm = wp & 3, wn = wp >> 2;
    int srow = tid >> 1, sc = (tid & 1) * 16;
    float* asd = As + srow * LDA + sc;
    float* bsd = Bs + srow * LDA + sc;
    const float* ag = arow + sc;
    const float* bg = brow + sc;
    // prologue: stage k0=0 into buffer 0
    #pragma unroll
    for (int q = 0; q < 16; q += 4) { cp16(asd + q, ag + q); cp16(bsd + q, bg + q); }
    asm volatile("cp.async.commit_group;");
    int buf = 0;
    #pragma unroll
    for (int k0 = 0; k0 < HH; k0 += BK) {
        if (k0 + BK < HH) {
            int nb = buf ^ 1;
            #pragma unroll
            for (int q = 0; q < 16; q += 4) {
                cp16(asd + nb * BUFO + q, ag + k0 + BK + q);
                cp16(bsd + nb * BUFO + q, bg + k0 + BK + q);
            }
            asm volatile("cp.async.commit_group;");
            asm volatile("cp.async.wait_group 1;" ::: "memory");
        } else {
            asm volatile("cp.async.wait_group 0;" ::: "memory");
        }
        __syncthreads();
        float* Ab = As + buf * BUFO;
        float* Bb = Bs + buf * BUFO;
        #pragma unroll
        for (int kk = 0; kk < BK; kk += 8) {
            FragA a0, a1; FragB bf[4];
            wmma::load_matrix_sync(a0, &Ab[(wm * 32)      * LDA + kk], LDA);
            wmma::load_matrix_sync(a1, &Ab[(wm * 32 + 16) * LDA + kk], LDA);
            cvtA(a0); cvtA(a1);
            #pragma unroll
            for (int j = 0; j < 4; j++) {
                wmma::load_matrix_sync(bf[j], &Bb[(wn * 64 + j * 16) * LDA + kk], LDA);
                cvtB(bf[j]);
            }
            #pragma unroll
            for (int j = 0; j < 4; j++) {
                wmma::mma_sync(c[0][j], a0, bf[j], c[0][j]);
                wmma::mma_sync(c[1][j], a1, bf[j], c[1][j]);
            }
        }
        __syncthreads();
        buf ^= 1;
    }
}

#define FRAG_INIT(c)                                     \
    _Pragma("unroll")                                    \
    for (int i = 0; i < 2; i++)                          \
        _Pragma("unroll")                                \
        for (int j = 0; j < 4; j++) wmma::fill_fragment(c[i][j], 0.f);

#define FRAG_TO_CS(c, Cs, wm, wn)                                                  \
    _Pragma("unroll")                                                              \
    for (int i = 0; i < 2; i++)                                                    \
        _Pragma("unroll")                                                          \
        for (int j = 0; j < 4; j++)                                                \
            wmma::store_matrix_sync(&Cs[(wm * 32 + i * 16) * LDC + wn * 64 + j * 16], \
                                    c[i][j], LDC, wmma::mem_row_major);

// ---------------- prep: stable descending sort + targets ----------------
__global__ void k_prep(const int* __restrict__ w, const int* __restrict__ cap,
                       float* __restrict__ out, long long out_size) {
    __shared__ int lens[BB];
    int i = threadIdx.x;
    lens[i] = cap[i];
    __syncthreads();
    int li = lens[i];
    int rank = 0;
    #pragma unroll 8
    for (int j = 0; j < BB; j++) {
        int lj = lens[j];
        rank += (lj > li) || (lj == li && j < i);
    }
    g_order[rank]  = i;
    g_declen[rank] = li - 1;
    __syncthreads();

    if (i < TT) {
        int c = 0;
        for (int j = 0; j < BB; j++) c += (g_declen[j] > i);
        g_cnt[i] = c;
    }

    long long PRED = (long long)BB * ML * VV;
    if (out_size >= PRED + (long long)BB * TT + BB) {
        int src = g_order[i];
        for (int k = 0; k < TT; k++)
            out[PRED + (long long)i * TT + k] = (float)w[src * ML + k + 1];
        out[PRED + (long long)BB * TT + i] = (float)g_declen[i];
    }
}

__global__ void k_init() {
    int i = blockIdx.x * blockDim.x + threadIdx.x;
    if (i < BB * HH) {
        g_hbuf[0][i] = 0.f;
        g_hbuf[1][i] = 0.f;
        g_cc[i] = 0.f;
    }
    if (i < NROWS) g_rowsum[i] = 0.f;
    if (i == 0) { g_barcnt = 0; g_barflag = 0; }
}

// ---- image projection: gp[b][n] = gimg[order[b]] . W_ih[n][0:512] ----
__global__ __launch_bounds__(256) void k_gproj(const float* __restrict__ gimg,
                                               const float* __restrict__ Wih) {
    extern __shared__ float dsm[];
    int tid = threadIdx.x;
    int m0 = blockIdx.y * 128, n0 = blockIdx.x * 128;
    int srow = tid >> 1;
    int wp = tid >> 5, wm = wp & 3, wn = wp >> 2;
    const float* arow = gimg + (size_t)g_order[m0 + srow] * HH;
    const float* brow = Wih + (size_t)(n0 + srow) * 1024;
    FragC c[2][4];
    FRAG_INIT(c);
    gemm_k512(arow, brow, dsm, dsm + 2 * BUFO, c, tid);
    #pragma unroll
    for (int i = 0; i < 2; i++)
        #pragma unroll
        for (int j = 0; j < 4; j++)
            wmma::store_matrix_sync(g_gp + (size_t)(m0 + wm * 32 + i * 16) * G4
                                         + n0 + wn * 64 + j * 16,
                                    c[i][j], G4, wmma::mem_row_major);
}

// ---- embedding projection + fold: xp = emb[word].W_ih[:,512:] + gp + bih + bhh
__global__ __launch_bounds__(256) void k_xproj(const int* __restrict__ w,
                                               const float* __restrict__ emb,
                                               const float* __restrict__ Wih,
                                               const float* __restrict__ bih,
                                               const float* __restrict__ bhh) {
    extern __shared__ float dsm[];
    int tid = threadIdx.x;
    int m0 = blockIdx.y * 128;
    int t = m0 >> 8, b0 = m0 & 255;
    int cnt = g_cnt[t];
    if (b0 >= cnt) return;
    int n0 = blockIdx.x * 128;
    int srow = tid >> 1;
    int wp = tid >> 5, wm = wp & 3, wn = wp >> 2;
    int word = w[g_order[b0 + srow] * ML + t];
    const float* arow = emb + (size_t)word * HH;
    const float* brow = Wih + (size_t)(n0 + srow) * 1024 + 512;
    FragC c[2][4];
    FRAG_INIT(c);
    gemm_k512(arow, brow, dsm, dsm + 2 * BUFO, c, tid);
    float* Cs = dsm;
    FRAG_TO_CS(c, Cs, wm, wn);
    __syncthreads();
    int row = tid >> 1, cb = (tid & 1) * 64;
    int b = b0 + row;
    if (b < cnt) {
        size_t xb = (size_t)(m0 + row) * G4;
        #pragma unroll
        for (int q = 0; q < 16; q++) {
            int n = n0 + cb + q * 4;
            float4 cv = *(const float4*)&Cs[row * LDC + cb + q * 4];
            float4 gp = *(const float4*)(g_gp + (size_t)b * G4 + n);
            float4 b1 = *(const float4*)(bih + n);
            float4 b2 = *(const float4*)(bhh + n);
            float4 v;
            v.x = cv.x + gp.x + b1.x + b2.x;
            v.y = cv.y + gp.y + b1.y + b2.y;
            v.z = cv.z + gp.z + b1.z + b2.z;
            v.w = cv.w + gp.w + b1.w + b2.w;
            *(float4*)(g_xp + xb + n) = v;
        }
    }
}

// ---- persistent recurrent kernel: all 30 steps, grid barrier between ----
__global__ __launch_bounds__(256) void k_steps(const float* __restrict__ Whh) {
    extern __shared__ float dsm[];
    int tid = threadIdx.x;
    int h0 = blockIdx.x * 32;          // 16 h-tiles
    int b0 = blockIdx.y * 128;         // 2 b-tiles
    int srow = tid >> 1;
    int wp = tid >> 5, wm = wp & 3, wn = wp >> 2;
    int gate = srow >> 5, hh_s = srow & 31;
    const float* brow = Whh + (size_t)(gate * 512 + h0 + hh_s) * HH;

    for (int t = 0; t < TT; t++) {
        int cnt = g_cnt[t];
        if (b0 < cnt) {
            FragC c[2][4];
            FRAG_INIT(c);
            const float* arow = g_hbuf[t & 1] + (size_t)(b0 + srow) * HH;
            gemm_k512(arow, brow, dsm, dsm + 2 * BUFO, c, tid);
            float* Cs = dsm;
            FRAG_TO_CS(c, Cs, wm, wn);
            __syncthreads();
            // LSTM elementwise: 128 b x 32 h
            #pragma unroll
            for (int it = 0; it < 16; it++) {
                int p = it * 256 + tid;
                int row = p >> 5;
                int hh = p & 31;
                int b = b0 + row;
                if (b >= cnt) continue;
                size_t xpb = (size_t)(t * BB + b) * G4 + h0 + hh;
                float iv = Cs[row * LDC + 0  + hh] + g_xp[xpb];
                float fv = Cs[row * LDC + 32 + hh] + g_xp[xpb + 512];
                float gv = Cs[row * LDC + 64 + hh] + g_xp[xpb + 1024];
                float ov = Cs[row * LDC + 96 + hh] + g_xp[xpb + 1536];
                iv = 1.f / (1.f + __expf(-iv));
                fv = 1.f / (1.f + __expf(-fv));
                ov = 1.f / (1.f + __expf(-ov));
                gv = tanhf(gv);
                int hidx = b * HH + h0 + hh;
                float cn = fv * g_cc[hidx] + iv * gv;
                float hn = ov * tanhf(cn);
                g_cc[hidx] = cn;
                g_hbuf[(t + 1) & 1][hidx] = hn;
                g_hall[(size_t)(t * BB + b) * HH + h0 + hh] = hn;
            }
            __syncthreads();
        }
        // grid barrier (32 co-resident blocks)
        __threadfence();
        if (tid == 0) {
            int v = atomicAdd(&g_barcnt, 1);
            if (v == NBLK - 1) {
                atomicExch(&g_barcnt, 0);
                __threadfence();
                atomicExch(&g_barflag, t + 1);
            } else {
                while (atomicAdd(&g_barflag, 0) < t + 1) {}
            }
        }
        __syncthreads();
    }
}

// ---- vocab projection: logits -> out (in place) + rowsum of exp ----
__global__ __launch_bounds__(256) void k_out1(const float* __restrict__ Wout,
                                              const float* __restrict__ bout,
                                              float* __restrict__ out) {
    extern __shared__ float dsm[];
    int tid = threadIdx.x;
    int m0 = blockIdx.y * 128;
    int t = m0 >> 8, b0 = m0 & 255;
    int cnt = g_cnt[t];
    if (b0 >= cnt) return;
    int n0 = blockIdx.x * 128;
    int srow = tid >> 1;
    int wp = tid >> 5, wm = wp & 3, wn = wp >> 2;
    const float* arow = g_hall + (size_t)(m0 + srow) * HH;
    int nb = n0 + srow;
    const float* brow = Wout + (size_t)(nb < VV ? nb : VV - 1) * HH;
    FragC c[2][4];
    FRAG_INIT(c);
    gemm_k512(arow, brow, dsm, dsm + 2 * BUFO, c, tid);
    float* Cs = dsm;
    FRAG_TO_CS(c, Cs, wm, wn);
    __syncthreads();

    int row = tid >> 1, cb = (tid & 1) * 64;
    int b = b0 + row;
    if (b < cnt) {
        size_t obase = ((size_t)b * ML + t) * VV;
        float psum = 0.f;
        #pragma unroll
        for (int q = 0; q < 16; q++) {
            int n = n0 + cb + q * 4;
            if (n < VV) {
                float4 cv = *(const float4*)&Cs[row * LDC + cb + q * 4];
                float4 bo = *(const float4*)(bout + n);
                float4 v;
                v.x = cv.x + bo.x; v.y = cv.y + bo.y;
                v.z = cv.z + bo.z; v.w = cv.w + bo.w;
                *(float4*)(out + obase + n) = v;
                psum += __expf(v.x) + __expf(v.y) + __expf(v.z) + __expf(v.w);
            }
        }
        atomicAdd(&g_rowsum[m0 + row], psum);
    }
}

// ---- final: in-place log-softmax correction ----
__global__ __launch_bounds__(256) void k_out2(float* __restrict__ out) {
    long long idx = (long long)blockIdx.x * 256 + threadIdx.x;
    const int perRow = VV / 4;
    int r = (int)(idx / perRow);
    if (r >= NROWS) return;
    int v4 = (int)(idx % perRow);
    int t = r >> 8, b = r & 255;
    if (b >= g_cnt[t]) return;
    float ls = logf(g_rowsum[r]);
    size_t p = ((size_t)b * ML + t) * VV + v4 * 4;
    float4 lv = *(const float4*)(out + p);
    float4 o;
    o.x = lv.x - ls; o.y = lv.y - ls; o.z = lv.z - ls; o.w = lv.w - ls;
    *(float4*)(out + p) = o;
}

// ---------------- launch ----------------
extern "C" void kernel_launch(void* const* d_in, const int* in_sizes, int n_in,
                              void* d_out, int out_size) {
    const float* gimg = (const float*)d_in[0];
    const int*   w    = (const int*)d_in[1];
    const int*   cap  = (const int*)d_in[2];
    const float* emb  = (const float*)d_in[3];
    const float* Wih  = (const float*)d_in[4];
    const float* Whh  = (const float*)d_in[5];
    const float* bih  = (const float*)d_in[6];
    const float* bhh  = (const float*)d_in[7];
    const float* Wout = (const float*)d_in[8];
    const float* bout = (const float*)d_in[9];
    float* out = (float*)d_out;

    static int attr_done = 0;
    if (!attr_done) {
        cudaFuncSetAttribute(k_gproj, cudaFuncAttributeMaxDynamicSharedMemorySize, DSMEM_BYTES);
        cudaFuncSetAttribute(k_xproj, cudaFuncAttributeMaxDynamicSharedMemorySize, DSMEM_BYTES);
        cudaFuncSetAttribute(k_steps, cudaFuncAttributeMaxDynamicSharedMemorySize, DSMEM_BYTES);
        cudaFuncSetAttribute(k_out1,  cudaFuncAttributeMaxDynamicSharedMemorySize, DSMEM_BYTES);
        attr_done = 1;
    }

    size_t PRED = (size_t)BB * ML * VV;
    cudaMemsetAsync(d_out, 0, PRED * sizeof(float), 0);

    k_prep<<<1, 256>>>(w, cap, out, (long long)out_size);
    k_init<<<512, 256>>>();
    k_gproj<<<dim3(16, 2), 256, DSMEM_BYTES>>>(gimg, Wih);
    k_xproj<<<dim3(16, 60), 256, DSMEM_BYTES>>>(w, emb, Wih, bih, bhh);
    k_steps<<<dim3(16, 2), 256, DSMEM_BYTES>>>(Whh);
    k_out1<<<dim3(79, 60), 256, DSMEM_BYTES>>>(Wout, bout, out);
    k_out2<<<75000, 256>>>(out);
}

// round 4
// speedup vs baseline: 1.2087x; 1.2087x over previous
#include <cuda_runtime.h>
#include <mma.h>
#include <math.h>

using namespace nvcuda;

// Problem constants
#define BB 256
#define TT 30
#define ML 31
#define VV 10000
#define HH 512
#define G4 2048            // 4*H
#define NROWS 7680         // TT*BB
#define BK 32
#define LDA 36             // shared lda (32 + 4 pad) -> 144B rows (16B aligned)
#define LDC 132            // shared C ld (128 + 4 pad)
#define BUFO (128 * LDA)   // floats per stage buffer
#define DSMEM_BYTES (4 * BUFO * 4)   // 73728 B: As[2] + Bs[2]; Cs reuses
#define NBLK 32            // persistent-step grid size

// ---------------- device scratch ----------------
__device__ int   g_order[BB];
__device__ int   g_declen[BB];
__device__ int   g_cnt[TT];
__device__ float g_gp[BB * G4];
__device__ float g_xp[(size_t)NROWS * G4];       // emb-proj + gp + biases (pre-folded)
__device__ float g_hbuf[2][BB * HH];
__device__ float g_cc[BB * HH];
__device__ float g_hall[(size_t)NROWS * HH];
__device__ float g_rowsum[NROWS];
__device__ int   g_barcnt;
__device__ int   g_barflag;

typedef wmma::fragment<wmma::matrix_a, 16, 16, 8, wmma::precision::tf32, wmma::row_major> FragA;
typedef wmma::fragment<wmma::matrix_b, 16, 16, 8, wmma::precision::tf32, wmma::col_major> FragB;
typedef wmma::fragment<wmma::accumulator, 16, 16, 8, float> FragC;

__device__ __forceinline__ void cvtA(FragA& f) {
    #pragma unroll
    for (int q = 0; q < f.num_elements; q++) f.x[q] = wmma::__float_to_tf32(f.x[q]);
}
__device__ __forceinline__ void cvtB(FragB& f) {
    #pragma unroll
    for (int q = 0; q < f.num_elements; q++) f.x[q] = wmma::__float_to_tf32(f.x[q]);
}

__device__ __forceinline__ void cp16(float* s, const float* g) {
    unsigned d = (unsigned)__cvta_generic_to_shared(s);
    asm volatile("cp.async.cg.shared.global [%0], [%1], 16;" :: "r"(d), "l"(g));
}

// ---- common pipelined GEMM: C[128x128] += A[128x512] * B[128x512]^T ----
// arow/brow: this thread's staged row base (row = tid>>1), K-contiguous.
// CRITICAL: k0 loop is NOT unrolled (register pressure); kk loop IS.
__device__ __forceinline__ void gemm_k512(const float* arow, const float* brow,
                                          float* As, float* Bs,
                                          FragC (&c)[2][4], int tid) {
    int wp = tid >> 5, wm = wp & 3, wn = wp >> 2;
    int srow = tid >> 1, sc = (tid & 1) * 16;
    float* asd = As + srow * LDA + sc;
    float* bsd = Bs + srow * LDA + sc;
    const float* ag = arow + sc;
    const float* bg = brow + sc;
    // prologue: stage k0=0 into buffer 0
    #pragma unroll
    for (int q = 0; q < 16; q += 4) { cp16(asd + q, ag + q); cp16(bsd + q, bg + q); }
    asm volatile("cp.async.commit_group;");
    int buf = 0;
    #pragma unroll 1
    for (int k0 = 0; k0 < HH; k0 += BK) {
        if (k0 + BK < HH) {
            int nb = buf ^ 1;
            #pragma unroll
            for (int q = 0; q < 16; q += 4) {
                cp16(asd + nb * BUFO + q, ag + k0 + BK + q);
                cp16(bsd + nb * BUFO + q, bg + k0 + BK + q);
            }
            asm volatile("cp.async.commit_group;");
            asm volatile("cp.async.wait_group 1;" ::: "memory");
        } else {
            asm volatile("cp.async.wait_group 0;" ::: "memory");
        }
        __syncthreads();
        float* Ab = As + buf * BUFO;
        float* Bb = Bs + buf * BUFO;
        #pragma unroll
        for (int kk = 0; kk < BK; kk += 8) {
            FragA a0, a1; FragB bf[4];
            wmma::load_matrix_sync(a0, &Ab[(wm * 32)      * LDA + kk], LDA);
            wmma::load_matrix_sync(a1, &Ab[(wm * 32 + 16) * LDA + kk], LDA);
            cvtA(a0); cvtA(a1);
            #pragma unroll
            for (int j = 0; j < 4; j++) {
                wmma::load_matrix_sync(bf[j], &Bb[(wn * 64 + j * 16) * LDA + kk], LDA);
                cvtB(bf[j]);
            }
            #pragma unroll
            for (int j = 0; j < 4; j++) {
                wmma::mma_sync(c[0][j], a0, bf[j], c[0][j]);
                wmma::mma_sync(c[1][j], a1, bf[j], c[1][j]);
            }
        }
        __syncthreads();
        buf ^= 1;
    }
}

#define FRAG_INIT(c)                                     \
    _Pragma("unroll")                                    \
    for (int i = 0; i < 2; i++)                          \
        _Pragma("unroll")                                \
        for (int j = 0; j < 4; j++) wmma::fill_fragment(c[i][j], 0.f);

#define FRAG_TO_CS(c, Cs, wm, wn)                                                  \
    _Pragma("unroll")                                                              \
    for (int i = 0; i < 2; i++)                                                    \
        _Pragma("unroll")                                                          \
        for (int j = 0; j < 4; j++)                                                \
            wmma::store_matrix_sync(&Cs[(wm * 32 + i * 16) * LDC + wn * 64 + j * 16], \
                                    c[i][j], LDC, wmma::mem_row_major);

// ---------------- prep: stable descending sort + targets ----------------
__global__ void k_prep(const int* __restrict__ w, const int* __restrict__ cap,
                       float* __restrict__ out, long long out_size) {
    __shared__ int lens[BB];
    int i = threadIdx.x;
    lens[i] = cap[i];
    __syncthreads();
    int li = lens[i];
    int rank = 0;
    #pragma unroll 8
    for (int j = 0; j < BB; j++) {
        int lj = lens[j];
        rank += (lj > li) || (lj == li && j < i);
    }
    g_order[rank]  = i;
    g_declen[rank] = li - 1;
    __syncthreads();

    if (i < TT) {
        int c = 0;
        for (int j = 0; j < BB; j++) c += (g_declen[j] > i);
        g_cnt[i] = c;
    }

    long long PRED = (long long)BB * ML * VV;
    if (out_size >= PRED + (long long)BB * TT + BB) {
        int src = g_order[i];
        for (int k = 0; k < TT; k++)
            out[PRED + (long long)i * TT + k] = (float)w[src * ML + k + 1];
        out[PRED + (long long)BB * TT + i] = (float)g_declen[i];
    }
}

__global__ void k_init() {
    int i = blockIdx.x * blockDim.x + threadIdx.x;
    if (i < BB * HH) {
        g_hbuf[0][i] = 0.f;
        g_hbuf[1][i] = 0.f;
        g_cc[i] = 0.f;
    }
    if (i < NROWS) g_rowsum[i] = 0.f;
    if (i == 0) { g_barcnt = 0; g_barflag = 0; }
}

// ---- image projection: gp[b][n] = gimg[order[b]] . W_ih[n][0:512] ----
__global__ __launch_bounds__(256, 2) void k_gproj(const float* __restrict__ gimg,
                                                  const float* __restrict__ Wih) {
    extern __shared__ float dsm[];
    int tid = threadIdx.x;
    int m0 = blockIdx.y * 128, n0 = blockIdx.x * 128;
    int srow = tid >> 1;
    int wp = tid >> 5, wm = wp & 3, wn = wp >> 2;
    const float* arow = gimg + (size_t)g_order[m0 + srow] * HH;
    const float* brow = Wih + (size_t)(n0 + srow) * 1024;
    FragC c[2][4];
    FRAG_INIT(c);
    gemm_k512(arow, brow, dsm, dsm + 2 * BUFO, c, tid);
    #pragma unroll
    for (int i = 0; i < 2; i++)
        #pragma unroll
        for (int j = 0; j < 4; j++)
            wmma::store_matrix_sync(g_gp + (size_t)(m0 + wm * 32 + i * 16) * G4
                                         + n0 + wn * 64 + j * 16,
                                    c[i][j], G4, wmma::mem_row_major);
}

// ---- embedding projection + fold: xp = emb[word].W_ih[:,512:] + gp + bih + bhh
__global__ __launch_bounds__(256, 2) void k_xproj(const int* __restrict__ w,
                                                  const float* __restrict__ emb,
                                                  const float* __restrict__ Wih,
                                                  const float* __restrict__ bih,
                                                  const float* __restrict__ bhh) {
    extern __shared__ float dsm[];
    int tid = threadIdx.x;
    int m0 = blockIdx.y * 128;
    int t = m0 >> 8, b0 = m0 & 255;
    int cnt = g_cnt[t];
    if (b0 >= cnt) return;
    int n0 = blockIdx.x * 128;
    int srow = tid >> 1;
    int wp = tid >> 5, wm = wp & 3, wn = wp >> 2;
    int word = w[g_order[b0 + srow] * ML + t];
    const float* arow = emb + (size_t)word * HH;
    const float* brow = Wih + (size_t)(n0 + srow) * 1024 + 512;
    FragC c[2][4];
    FRAG_INIT(c);
    gemm_k512(arow, brow, dsm, dsm + 2 * BUFO, c, tid);
    float* Cs = dsm;
    FRAG_TO_CS(c, Cs, wm, wn);
    __syncthreads();
    int row = tid >> 1, cb = (tid & 1) * 64;
    int b = b0 + row;
    if (b < cnt) {
        size_t xb = (size_t)(m0 + row) * G4;
        #pragma unroll
        for (int q = 0; q < 16; q++) {
            int n = n0 + cb + q * 4;
            float4 cv = *(const float4*)&Cs[row * LDC + cb + q * 4];
            float4 gp = *(const float4*)(g_gp + (size_t)b * G4 + n);
            float4 b1 = *(const float4*)(bih + n);
            float4 b2 = *(const float4*)(bhh + n);
            float4 v;
            v.x = cv.x + gp.x + b1.x + b2.x;
            v.y = cv.y + gp.y + b1.y + b2.y;
            v.z = cv.z + gp.z + b1.z + b2.z;
            v.w = cv.w + gp.w + b1.w + b2.w;
            *(float4*)(g_xp + xb + n) = v;
        }
    }
}

// ---- persistent recurrent kernel: all 30 steps, grid barrier between ----
__global__ __launch_bounds__(256, 2) void k_steps(const float* __restrict__ Whh) {
    extern __shared__ float dsm[];
    int tid = threadIdx.x;
    int h0 = blockIdx.x * 32;          // 16 h-tiles
    int b0 = blockIdx.y * 128;         // 2 b-tiles
    int srow = tid >> 1;
    int wp = tid >> 5, wm = wp & 3, wn = wp >> 2;
    int gate = srow >> 5, hh_s = srow & 31;
    const float* brow = Whh + (size_t)(gate * 512 + h0 + hh_s) * HH;

    for (int t = 0; t < TT; t++) {
        int cnt = g_cnt[t];
        if (b0 < cnt) {
            FragC c[2][4];
            FRAG_INIT(c);
            const float* arow = g_hbuf[t & 1] + (size_t)(b0 + srow) * HH;
            gemm_k512(arow, brow, dsm, dsm + 2 * BUFO, c, tid);
            float* Cs = dsm;
            FRAG_TO_CS(c, Cs, wm, wn);
            __syncthreads();
            // LSTM elementwise: 128 b x 32 h
            #pragma unroll
            for (int it = 0; it < 16; it++) {
                int p = it * 256 + tid;
                int row = p >> 5;
                int hh = p & 31;
                int b = b0 + row;
                if (b >= cnt) continue;
                size_t xpb = (size_t)(t * BB + b) * G4 + h0 + hh;
                float iv = Cs[row * LDC + 0  + hh] + g_xp[xpb];
                float fv = Cs[row * LDC + 32 + hh] + g_xp[xpb + 512];
                float gv = Cs[row * LDC + 64 + hh] + g_xp[xpb + 1024];
                float ov = Cs[row * LDC + 96 + hh] + g_xp[xpb + 1536];
                iv = 1.f / (1.f + __expf(-iv));
                fv = 1.f / (1.f + __expf(-fv));
                ov = 1.f / (1.f + __expf(-ov));
                gv = tanhf(gv);
                int hidx = b * HH + h0 + hh;
                float cn = fv * g_cc[hidx] + iv * gv;
                float hn = ov * tanhf(cn);
                g_cc[hidx] = cn;
                g_hbuf[(t + 1) & 1][hidx] = hn;
                g_hall[(size_t)(t * BB + b) * HH + h0 + hh] = hn;
            }
            __syncthreads();
        }
        // grid barrier (32 co-resident blocks)
        __threadfence();
        if (tid == 0) {
            int v = atomicAdd(&g_barcnt, 1);
            if (v == NBLK - 1) {
                atomicExch(&g_barcnt, 0);
                __threadfence();
                atomicExch(&g_barflag, t + 1);
            } else {
                while (atomicAdd(&g_barflag, 0) < t + 1) {}
            }
        }
        __syncthreads();
    }
}

// ---- vocab projection: logits -> out (in place) + rowsum of exp ----
__global__ __launch_bounds__(256, 2) void k_out1(const float* __restrict__ Wout,
                                                 const float* __restrict__ bout,
                                                 float* __restrict__ out) {
    extern __shared__ float dsm[];
    int tid = threadIdx.x;
    int m0 = blockIdx.y * 128;
    int t = m0 >> 8, b0 = m0 & 255;
    int cnt = g_cnt[t];
    if (b0 >= cnt) return;
    int n0 = blockIdx.x * 128;
    int srow = tid >> 1;
    int wp = tid >> 5, wm = wp & 3, wn = wp >> 2;
    const float* arow = g_hall + (size_t)(m0 + srow) * HH;
    int nb = n0 + srow;
    const float* brow = Wout + (size_t)(nb < VV ? nb : VV - 1) * HH;
    FragC c[2][4];
    FRAG_INIT(c);
    gemm_k512(arow, brow, dsm, dsm + 2 * BUFO, c, tid);
    float* Cs = dsm;
    FRAG_TO_CS(c, Cs, wm, wn);
    __syncthreads();

    int row = tid >> 1, cb = (tid & 1) * 64;
    int b = b0 + row;
    if (b < cnt) {
        size_t obase = ((size_t)b * ML + t) * VV;
        float psum = 0.f;
        #pragma unroll
        for (int q = 0; q < 16; q++) {
            int n = n0 + cb + q * 4;
            if (n < VV) {
                float4 cv = *(const float4*)&Cs[row * LDC + cb + q * 4];
                float4 bo = *(const float4*)(bout + n);
                float4 v;
                v.x = cv.x + bo.x; v.y = cv.y + bo.y;
                v.z = cv.z + bo.z; v.w = cv.w + bo.w;
                *(float4*)(out + obase + n) = v;
                psum += __expf(v.x) + __expf(v.y) + __expf(v.z) + __expf(v.w);
            }
        }
        atomicAdd(&g_rowsum[m0 + row], psum);
    }
}

// ---- final: full-output pass; zeros inactive/pad, log-softmax for active ----
__global__ __launch_bounds__(256) void k_out2(float* __restrict__ out) {
    long long idx = (long long)blockIdx.x * 256 + threadIdx.x;
    const int perRow = VV / 4;                 // 2500 float4 per row
    const long long TOT = (long long)BB * ML * perRow;
    if (idx >= TOT) return;
    int r = (int)(idx / perRow);               // r = b*31 + t
    int v4 = (int)(idx % perRow);
    int b = r / ML, t = r - b * ML;
    size_t p = (size_t)r * VV + v4 * 4;
    bool active = (t < TT) && (b < g_cnt[t]);
    float4 o = make_float4(0.f, 0.f, 0.f, 0.f);
    if (active) {
        float ls = logf(g_rowsum[t * BB + b]);
        float4 lv = *(const float4*)(out + p);
        o.x = lv.x - ls; o.y = lv.y - ls; o.z = lv.z - ls; o.w = lv.w - ls;
    }
    *(float4*)(out + p) = o;
}

// ---------------- launch ----------------
extern "C" void kernel_launch(void* const* d_in, const int* in_sizes, int n_in,
                              void* d_out, int out_size) {
    const float* gimg = (const float*)d_in[0];
    const int*   w    = (const int*)d_in[1];
    const int*   cap  = (const int*)d_in[2];
    const float* emb  = (const float*)d_in[3];
    const float* Wih  = (const float*)d_in[4];
    const float* Whh  = (const float*)d_in[5];
    const float* bih  = (const float*)d_in[6];
    const float* bhh  = (const float*)d_in[7];
    const float* Wout = (const float*)d_in[8];
    const float* bout = (const float*)d_in[9];
    float* out = (float*)d_out;

    static int attr_done = 0;
    if (!attr_done) {
        cudaFuncSetAttribute(k_gproj, cudaFuncAttributeMaxDynamicSharedMemorySize, DSMEM_BYTES);
        cudaFuncSetAttribute(k_xproj, cudaFuncAttributeMaxDynamicSharedMemorySize, DSMEM_BYTES);
        cudaFuncSetAttribute(k_steps, cudaFuncAttributeMaxDynamicSharedMemorySize, DSMEM_BYTES);
        cudaFuncSetAttribute(k_out1,  cudaFuncAttributeMaxDynamicSharedMemorySize, DSMEM_BYTES);
        attr_done = 1;
    }

    k_prep<<<1, 256>>>(w, cap, out, (long long)out_size);
    k_init<<<512, 256>>>();
    k_gproj<<<dim3(16, 2), 256, DSMEM_BYTES>>>(gimg, Wih);
    k_xproj<<<dim3(16, 60), 256, DSMEM_BYTES>>>(w, emb, Wih, bih, bhh);
    k_steps<<<dim3(16, 2), 256, DSMEM_BYTES>>>(Whh);
    k_out1<<<dim3(79, 60), 256, DSMEM_BYTES>>>(Wout, bout, out);
    // full-output pass: 256*31*2500 float4 slots
    long long tot = (long long)BB * ML * (VV / 4);
    k_out2<<<(int)((tot + 255) / 256), 256>>>(out);
}

// round 5
// speedup vs baseline: 3.0168x; 2.4960x over previous
#include <cuda_runtime.h>
#include <cuda_bf16.h>
#include <mma.h>
#include <math.h>

using namespace nvcuda;

// Problem constants
#define BB 256
#define TT 30
#define ML 31
#define VV 10000
#define HH 512
#define G4 2048            // 4*H
#define NROWS 7680         // TT*BB
#define BKB 64             // K-chunk (bf16 elems)
#define LDAB 72            // shared lda in bf16 elems (64 + 8 pad) -> 144B rows
#define LDC 132            // shared C ld (floats, 128 + 4 pad)
#define BUFB (128 * LDAB)  // bf16 elems per stage buffer (9216)
#define DSMEM_BYTES (4 * BUFB * 2)   // 73728 B: As[2]+Bs[2]; Cs (67584 B) reuses
#define NBLK 32            // persistent-step grid size

typedef __nv_bfloat16 bf16;

// ---------------- device scratch ----------------
__device__ int   g_order[BB];
__device__ int   g_declen[BB];
__device__ int   g_cnt[TT];
__device__ float g_gp[BB * G4];
__device__ float g_xp[(size_t)NROWS * G4];       // emb-proj + gp + biases (pre-folded)
__device__ float g_cc[BB * HH];
__device__ float g_rowsum[NROWS];
__device__ int   g_barcnt;
__device__ int   g_barflag;
// bf16 operand copies
__device__ bf16  g_Wih_bf[G4 * 1024];
__device__ bf16  g_Whh_bf[G4 * HH];
__device__ bf16  g_Wout_bf[VV * HH];
__device__ bf16  g_emb_bf[VV * HH];
__device__ bf16  g_gimg_bf[BB * HH];
__device__ bf16  g_hbuf_bf[2][BB * HH];
__device__ bf16  g_hall_bf[(size_t)NROWS * HH];

typedef wmma::fragment<wmma::matrix_a, 16, 16, 16, bf16, wmma::row_major> FragA;
typedef wmma::fragment<wmma::matrix_b, 16, 16, 16, bf16, wmma::col_major> FragB;
typedef wmma::fragment<wmma::accumulator, 16, 16, 16, float> FragC;

__device__ __forceinline__ void cp16(void* s, const void* g) {
    unsigned d = (unsigned)__cvta_generic_to_shared(s);
    asm volatile("cp.async.cg.shared.global [%0], [%1], 16;" :: "r"(d), "l"(g));
}

// ---- common pipelined bf16 GEMM: C[128x128] += A[128x512] * B[128x512]^T ----
// arow/brow: this thread's staged row base (row = tid>>1), K-contiguous bf16.
// k0 loop NOT unrolled (register pressure); kk loop IS.
__device__ __forceinline__ void gemm_bf16(const bf16* arow, const bf16* brow,
                                          bf16* As, bf16* Bs,
                                          FragC (&c)[2][4], int tid) {
    int wp = tid >> 5, wm = wp & 3, wn = wp >> 2;
    int srow = tid >> 1, sc = (tid & 1) * 32;    // 32 bf16 = 64 B per thread
    bf16* asd = As + srow * LDAB + sc;
    bf16* bsd = Bs + srow * LDAB + sc;
    const bf16* ag = arow + sc;
    const bf16* bg = brow + sc;
    // prologue: stage k0=0 into buffer 0 (4 x 16B per matrix)
    #pragma unroll
    for (int q = 0; q < 32; q += 8) { cp16(asd + q, ag + q); cp16(bsd + q, bg + q); }
    asm volatile("cp.async.commit_group;");
    int buf = 0;
    #pragma unroll 1
    for (int k0 = 0; k0 < HH; k0 += BKB) {
        if (k0 + BKB < HH) {
            int nb = buf ^ 1;
            #pragma unroll
            for (int q = 0; q < 32; q += 8) {
                cp16(asd + nb * BUFB + q, ag + k0 + BKB + q);
                cp16(bsd + nb * BUFB + q, bg + k0 + BKB + q);
            }
            asm volatile("cp.async.commit_group;");
            asm volatile("cp.async.wait_group 1;" ::: "memory");
        } else {
            asm volatile("cp.async.wait_group 0;" ::: "memory");
        }
        __syncthreads();
        bf16* Ab = As + buf * BUFB;
        bf16* Bb = Bs + buf * BUFB;
        #pragma unroll
        for (int kk = 0; kk < BKB; kk += 16) {
            FragA a0, a1; FragB bf[4];
            wmma::load_matrix_sync(a0, &Ab[(wm * 32)      * LDAB + kk], LDAB);
            wmma::load_matrix_sync(a1, &Ab[(wm * 32 + 16) * LDAB + kk], LDAB);
            #pragma unroll
            for (int j = 0; j < 4; j++)
                wmma::load_matrix_sync(bf[j], &Bb[(wn * 64 + j * 16) * LDAB + kk], LDAB);
            #pragma unroll
            for (int j = 0; j < 4; j++) {
                wmma::mma_sync(c[0][j], a0, bf[j], c[0][j]);
                wmma::mma_sync(c[1][j], a1, bf[j], c[1][j]);
            }
        }
        __syncthreads();
        buf ^= 1;
    }
}

#define FRAG_INIT(c)                                     \
    _Pragma("unroll")                                    \
    for (int i = 0; i < 2; i++)                          \
        _Pragma("unroll")                                \
        for (int j = 0; j < 4; j++) wmma::fill_fragment(c[i][j], 0.f);

#define FRAG_TO_CS(c, Cs, wm, wn)                                                  \
    _Pragma("unroll")                                                              \
    for (int i = 0; i < 2; i++)                                                    \
        _Pragma("unroll")                                                          \
        for (int j = 0; j < 4; j++)                                                \
            wmma::store_matrix_sync(&Cs[(wm * 32 + i * 16) * LDC + wn * 64 + j * 16], \
                                    c[i][j], LDC, wmma::mem_row_major);

// ---------------- fp32 -> bf16 conversion of all GEMM operands ----------------
#define N_WIH (G4 * 1024)
#define N_WHH (G4 * HH)
#define N_WOUT (VV * HH)
#define N_EMB (VV * HH)
#define N_GIMG (BB * HH)
#define N_CVT2 ((N_WIH + N_WHH + N_WOUT + N_EMB + N_GIMG) / 2)

__global__ __launch_bounds__(256) void k_cvt(const float* __restrict__ Wih,
                                             const float* __restrict__ Whh,
                                             const float* __restrict__ Wout,
                                             const float* __restrict__ emb,
                                             const float* __restrict__ gimg) {
    long long i2 = (long long)blockIdx.x * 256 + threadIdx.x;
    if (i2 >= N_CVT2) return;
    long long i = i2 * 2;
    const float* src; bf16* dst; long long off;
    if (i < N_WIH)                       { src = Wih;  dst = g_Wih_bf;  off = i; }
    else if (i < (long long)N_WIH + N_WHH) { src = Whh;  dst = g_Whh_bf;  off = i - N_WIH; }
    else if (i < (long long)N_WIH + N_WHH + N_WOUT)
                                         { src = Wout; dst = g_Wout_bf; off = i - N_WIH - N_WHH; }
    else if (i < (long long)N_WIH + N_WHH + N_WOUT + N_EMB)
                                         { src = emb;  dst = g_emb_bf;  off = i - N_WIH - N_WHH - N_WOUT; }
    else                                 { src = gimg; dst = g_gimg_bf; off = i - N_WIH - N_WHH - N_WOUT - N_EMB; }
    float2 v = *(const float2*)(src + off);
    __nv_bfloat162 o = __floats2bfloat162_rn(v.x, v.y);
    *(__nv_bfloat162*)(dst + off) = o;
}

// ---------------- prep: stable descending sort + targets ----------------
__global__ void k_prep(const int* __restrict__ w, const int* __restrict__ cap,
                       float* __restrict__ out, long long out_size) {
    __shared__ int lens[BB];
    int i = threadIdx.x;
    lens[i] = cap[i];
    __syncthreads();
    int li = lens[i];
    int rank = 0;
    #pragma unroll 8
    for (int j = 0; j < BB; j++) {
        int lj = lens[j];
        rank += (lj > li) || (lj == li && j < i);
    }
    g_order[rank]  = i;
    g_declen[rank] = li - 1;
    __syncthreads();

    if (i < TT) {
        int c = 0;
        for (int j = 0; j < BB; j++) c += (g_declen[j] > i);
        g_cnt[i] = c;
    }

    long long PRED = (long long)BB * ML * VV;
    if (out_size >= PRED + (long long)BB * TT + BB) {
        int src = g_order[i];
        for (int k = 0; k < TT; k++)
            out[PRED + (long long)i * TT + k] = (float)w[src * ML + k + 1];
        out[PRED + (long long)BB * TT + i] = (float)g_declen[i];
    }
}

__global__ void k_init() {
    int i = blockIdx.x * blockDim.x + threadIdx.x;
    if (i < BB * HH) {
        g_hbuf_bf[0][i] = __float2bfloat16(0.f);
        g_hbuf_bf[1][i] = __float2bfloat16(0.f);
        g_cc[i] = 0.f;
    }
    if (i < NROWS) g_rowsum[i] = 0.f;
    if (i == 0) { g_barcnt = 0; g_barflag = 0; }
}

// ---- image projection: gp[b][n] = gimg[order[b]] . W_ih[n][0:512] ----
__global__ __launch_bounds__(256, 2) void k_gproj() {
    extern __shared__ bf16 dsm[];
    int tid = threadIdx.x;
    int m0 = blockIdx.y * 128, n0 = blockIdx.x * 128;
    int srow = tid >> 1;
    int wp = tid >> 5, wm = wp & 3, wn = wp >> 2;
    const bf16* arow = g_gimg_bf + (size_t)g_order[m0 + srow] * HH;
    const bf16* brow = g_Wih_bf + (size_t)(n0 + srow) * 1024;
    FragC c[2][4];
    FRAG_INIT(c);
    gemm_bf16(arow, brow, dsm, dsm + 2 * BUFB, c, tid);
    #pragma unroll
    for (int i = 0; i < 2; i++)
        #pragma unroll
        for (int j = 0; j < 4; j++)
            wmma::store_matrix_sync(g_gp + (size_t)(m0 + wm * 32 + i * 16) * G4
                                         + n0 + wn * 64 + j * 16,
                                    c[i][j], G4, wmma::mem_row_major);
}

// ---- embedding projection + fold: xp = emb[word].W_ih[:,512:] + gp + bih + bhh
__global__ __launch_bounds__(256, 2) void k_xproj(const int* __restrict__ w,
                                                  const float* __restrict__ bih,
                                                  const float* __restrict__ bhh) {
    extern __shared__ bf16 dsm[];
    int tid = threadIdx.x;
    int m0 = blockIdx.y * 128;
    int t = m0 >> 8, b0 = m0 & 255;
    int cnt = g_cnt[t];
    if (b0 >= cnt) return;
    int n0 = blockIdx.x * 128;
    int srow = tid >> 1;
    int wp = tid >> 5, wm = wp & 3, wn = wp >> 2;
    int word = w[g_order[b0 + srow] * ML + t];
    const bf16* arow = g_emb_bf + (size_t)word * HH;
    const bf16* brow = g_Wih_bf + (size_t)(n0 + srow) * 1024 + 512;
    FragC c[2][4];
    FRAG_INIT(c);
    gemm_bf16(arow, brow, dsm, dsm + 2 * BUFB, c, tid);
    float* Cs = (float*)dsm;
    FRAG_TO_CS(c, Cs, wm, wn);
    __syncthreads();
    int row = tid >> 1, cb = (tid & 1) * 64;
    int b = b0 + row;
    if (b < cnt) {
        size_t xb = (size_t)(m0 + row) * G4;
        #pragma unroll
        for (int q = 0; q < 16; q++) {
            int n = n0 + cb + q * 4;
            float4 cv = *(const float4*)&Cs[row * LDC + cb + q * 4];
            float4 gp = *(const float4*)(g_gp + (size_t)b * G4 + n);
            float4 b1 = *(const float4*)(bih + n);
            float4 b2 = *(const float4*)(bhh + n);
            float4 v;
            v.x = cv.x + gp.x + b1.x + b2.x;
            v.y = cv.y + gp.y + b1.y + b2.y;
            v.z = cv.z + gp.z + b1.z + b2.z;
            v.w = cv.w + gp.w + b1.w + b2.w;
            *(float4*)(g_xp + xb + n) = v;
        }
    }
}

// ---- persistent recurrent kernel: all 30 steps, grid barrier between ----
__global__ __launch_bounds__(256, 2) void k_steps() {
    extern __shared__ bf16 dsm[];
    int tid = threadIdx.x;
    int h0 = blockIdx.x * 32;          // 16 h-tiles
    int b0 = blockIdx.y * 128;         // 2 b-tiles
    int srow = tid >> 1;
    int wp = tid >> 5, wm = wp & 3, wn = wp >> 2;
    int gate = srow >> 5, hh_s = srow & 31;
    const bf16* brow = g_Whh_bf + (size_t)(gate * 512 + h0 + hh_s) * HH;

    for (int t = 0; t < TT; t++) {
        int cnt = g_cnt[t];
        if (b0 < cnt) {
            FragC c[2][4];
            FRAG_INIT(c);
            const bf16* arow = g_hbuf_bf[t & 1] + (size_t)(b0 + srow) * HH;
            gemm_bf16(arow, brow, dsm, dsm + 2 * BUFB, c, tid);
            float* Cs = (float*)dsm;
            FRAG_TO_CS(c, Cs, wm, wn);
            __syncthreads();
            // LSTM elementwise: 128 b x 32 h
            #pragma unroll
            for (int it = 0; it < 16; it++) {
                int p = it * 256 + tid;
                int row = p >> 5;
                int hh = p & 31;
                int b = b0 + row;
                if (b >= cnt) continue;
                size_t xpb = (size_t)(t * BB + b) * G4 + h0 + hh;
                float iv = Cs[row * LDC + 0  + hh] + g_xp[xpb];
                float fv = Cs[row * LDC + 32 + hh] + g_xp[xpb + 512];
                float gv = Cs[row * LDC + 64 + hh] + g_xp[xpb + 1024];
                float ov = Cs[row * LDC + 96 + hh] + g_xp[xpb + 1536];
                iv = 1.f / (1.f + __expf(-iv));
                fv = 1.f / (1.f + __expf(-fv));
                ov = 1.f / (1.f + __expf(-ov));
                gv = tanhf(gv);
                int hidx = b * HH + h0 + hh;
                float cn = fv * g_cc[hidx] + iv * gv;
                float hn = ov * tanhf(cn);
                g_cc[hidx] = cn;
                bf16 hb = __float2bfloat16(hn);
                g_hbuf_bf[(t + 1) & 1][hidx] = hb;
                g_hall_bf[(size_t)(t * BB + b) * HH + h0 + hh] = hb;
            }
            __syncthreads();
        }
        // grid barrier (32 co-resident blocks)
        __threadfence();
        if (tid == 0) {
            int v = atomicAdd(&g_barcnt, 1);
            if (v == NBLK - 1) {
                atomicExch(&g_barcnt, 0);
                __threadfence();
                atomicExch(&g_barflag, t + 1);
            } else {
                while (atomicAdd(&g_barflag, 0) < t + 1) {}
            }
        }
        __syncthreads();
    }
}

// ---- vocab projection: logits -> out (in place) + rowsum of exp ----
__global__ __launch_bounds__(256, 2) void k_out1(const float* __restrict__ bout,
                                                 float* __restrict__ out) {
    extern __shared__ bf16 dsm[];
    int tid = threadIdx.x;
    int m0 = blockIdx.y * 128;
    int t = m0 >> 8, b0 = m0 & 255;
    int cnt = g_cnt[t];
    if (b0 >= cnt) return;
    int n0 = blockIdx.x * 128;
    int srow = tid >> 1;
    int wp = tid >> 5, wm = wp & 3, wn = wp >> 2;
    const bf16* arow = g_hall_bf + (size_t)(m0 + srow) * HH;
    int nb = n0 + srow;
    const bf16* brow = g_Wout_bf + (size_t)(nb < VV ? nb : VV - 1) * HH;
    FragC c[2][4];
    FRAG_INIT(c);
    gemm_bf16(arow, brow, dsm, dsm + 2 * BUFB, c, tid);
    float* Cs = (float*)dsm;
    FRAG_TO_CS(c, Cs, wm, wn);
    __syncthreads();

    int row = tid >> 1, cb = (tid & 1) * 64;
    int b = b0 + row;
    if (b < cnt) {
        size_t obase = ((size_t)b * ML + t) * VV;
        float psum = 0.f;
        #pragma unroll
        for (int q = 0; q < 16; q++) {
            int n = n0 + cb + q * 4;
            if (n < VV) {
                float4 cv = *(const float4*)&Cs[row * LDC + cb + q * 4];
                float4 bo = *(const float4*)(bout + n);
                float4 v;
                v.x = cv.x + bo.x; v.y = cv.y + bo.y;
                v.z = cv.z + bo.z; v.w = cv.w + bo.w;
                *(float4*)(out + obase + n) = v;
                psum += __expf(v.x) + __expf(v.y) + __expf(v.z) + __expf(v.w);
            }
        }
        atomicAdd(&g_rowsum[m0 + row], psum);
    }
}

// ---- final: full-output pass; zeros inactive/pad, log-softmax for active ----
__global__ __launch_bounds__(256) void k_out2(float* __restrict__ out) {
    long long idx = (long long)blockIdx.x * 256 + threadIdx.x;
    const int perRow = VV / 4;                 // 2500 float4 per row
    const long long TOT = (long long)BB * ML * perRow;
    if (idx >= TOT) return;
    int r = (int)(idx / perRow);               // r = b*31 + t
    int v4 = (int)(idx % perRow);
    int b = r / ML, t = r - b * ML;
    size_t p = (size_t)r * VV + v4 * 4;
    bool active = (t < TT) && (b < g_cnt[t]);
    float4 o = make_float4(0.f, 0.f, 0.f, 0.f);
    if (active) {
        float ls = logf(g_rowsum[t * BB + b]);
        float4 lv = *(const float4*)(out + p);
        o.x = lv.x - ls; o.y = lv.y - ls; o.z = lv.z - ls; o.w = lv.w - ls;
    }
    *(float4*)(out + p) = o;
}

// ---------------- launch ----------------
extern "C" void kernel_launch(void* const* d_in, const int* in_sizes, int n_in,
                              void* d_out, int out_size) {
    const float* gimg = (const float*)d_in[0];
    const int*   w    = (const int*)d_in[1];
    const int*   cap  = (const int*)d_in[2];
    const float* emb  = (const float*)d_in[3];
    const float* Wih  = (const float*)d_in[4];
    const float* Whh  = (const float*)d_in[5];
    const float* bih  = (const float*)d_in[6];
    const float* bhh  = (const float*)d_in[7];
    const float* Wout = (const float*)d_in[8];
    const float* bout = (const float*)d_in[9];
    float* out = (float*)d_out;

    static int attr_done = 0;
    if (!attr_done) {
        cudaFuncSetAttribute(k_gproj, cudaFuncAttributeMaxDynamicSharedMemorySize, DSMEM_BYTES);
        cudaFuncSetAttribute(k_xproj, cudaFuncAttributeMaxDynamicSharedMemorySize, DSMEM_BYTES);
        cudaFuncSetAttribute(k_steps, cudaFuncAttributeMaxDynamicSharedMemorySize, DSMEM_BYTES);
        cudaFuncSetAttribute(k_out1,  cudaFuncAttributeMaxDynamicSharedMemorySize, DSMEM_BYTES);
        attr_done = 1;
    }

    k_cvt<<<(int)((N_CVT2 + 255) / 256), 256>>>(Wih, Whh, Wout, emb, gimg);
    k_prep<<<1, 256>>>(w, cap, out, (long long)out_size);
    k_init<<<512, 256>>>();
    k_gproj<<<dim3(16, 2), 256, DSMEM_BYTES>>>();
    k_xproj<<<dim3(16, 60), 256, DSMEM_BYTES>>>(w, bih, bhh);
    k_steps<<<dim3(16, 2), 256, DSMEM_BYTES>>>();
    k_out1<<<dim3(79, 60), 256, DSMEM_BYTES>>>(bout, out);
    long long tot = (long long)BB * ML * (VV / 4);
    k_out2<<<(int)((tot + 255) / 256), 256>>>(out);
}

// round 7
// speedup vs baseline: 4.0984x; 1.3585x over previous
#include <cuda_runtime.h>
#include <cuda_bf16.h>
#include <mma.h>
#include <math.h>

using namespace nvcuda;

// Problem constants
#define BB 256
#define TT 30
#define ML 31
#define VV 10000
#define HH 512
#define G4 2048            // 4*H
#define NROWS 7680         // TT*BB
#define BKB 64             // K-chunk (bf16 elems)
#define LDAB 72            // shared lda in bf16 elems (64 + 8 pad) -> 144B rows
#define LDC 132            // shared C ld (floats, 128 + 4 pad)
#define LDC2 68            // shared C ld for 64-wide tiles
#define BUFB (128 * LDAB)  // bf16 elems per A stage buffer (9216)
#define BUFB2 (64 * LDAB)  // bf16 elems per B stage buffer in k_steps (4608)
#define DSMEM_BYTES (4 * BUFB * 2)            // 73728 B (128x128 GEMMs)
#define DSMEM_STEPS ((2*BUFB + 2*BUFB2) * 2)  // 55296 B (k_steps)
#define NBLK 64            // persistent-step grid size

typedef __nv_bfloat16 bf16;

// ---------------- device scratch ----------------
__device__ int   g_order[BB];
__device__ int   g_declen[BB];
__device__ int   g_cnt[TT];
__device__ int   g_rowmap[NROWS];   // packed active row -> t*256+b
__device__ int   g_ntot;            // number of active rows
__device__ float g_gp[BB * G4];
__device__ float g_xp[(size_t)NROWS * G4];       // emb-proj + gp + biases (pre-folded)
__device__ float g_cc[BB * HH];
__device__ float g_rowsum[NROWS];
__device__ int   g_barcnt;
__device__ int   g_barflag;
// bf16 operand copies
__device__ bf16  g_Wih_bf[G4 * 1024];
__device__ bf16  g_Whh_bf[G4 * HH];
__device__ bf16  g_Wout_bf[VV * HH];
__device__ bf16  g_emb_bf[VV * HH];
__device__ bf16  g_gimg_bf[BB * HH];
__device__ bf16  g_hbuf_bf[2][BB * HH];
__device__ bf16  g_hall_bf[(size_t)NROWS * HH];

typedef wmma::fragment<wmma::matrix_a, 16, 16, 16, bf16, wmma::row_major> FragA;
typedef wmma::fragment<wmma::matrix_b, 16, 16, 16, bf16, wmma::col_major> FragB;
typedef wmma::fragment<wmma::accumulator, 16, 16, 16, float> FragC;

__device__ __forceinline__ void cp16(void* s, const void* g) {
    unsigned d = (unsigned)__cvta_generic_to_shared(s);
    asm volatile("cp.async.cg.shared.global [%0], [%1], 16;" :: "r"(d), "l"(g));
}

// ---- common pipelined bf16 GEMM: C[128x128] += A[128x512] * B[128x512]^T ----
__device__ __forceinline__ void gemm_bf16(const bf16* arow, const bf16* brow,
                                          bf16* As, bf16* Bs,
                                          FragC (&c)[2][4], int tid) {
    int wp = tid >> 5, wm = wp & 3, wn = wp >> 2;
    int srow = tid >> 1, sc = (tid & 1) * 32;    // 32 bf16 = 64 B per thread
    bf16* asd = As + srow * LDAB + sc;
    bf16* bsd = Bs + srow * LDAB + sc;
    const bf16* ag = arow + sc;
    const bf16* bg = brow + sc;
    #pragma unroll
    for (int q = 0; q < 32; q += 8) { cp16(asd + q, ag + q); cp16(bsd + q, bg + q); }
    asm volatile("cp.async.commit_group;");
    int buf = 0;
    #pragma unroll 1
    for (int k0 = 0; k0 < HH; k0 += BKB) {
        if (k0 + BKB < HH) {
            int nb = buf ^ 1;
            #pragma unroll
            for (int q = 0; q < 32; q += 8) {
                cp16(asd + nb * BUFB + q, ag + k0 + BKB + q);
                cp16(bsd + nb * BUFB + q, bg + k0 + BKB + q);
            }
            asm volatile("cp.async.commit_group;");
            asm volatile("cp.async.wait_group 1;" ::: "memory");
        } else {
            asm volatile("cp.async.wait_group 0;" ::: "memory");
        }
        __syncthreads();
        bf16* Ab = As + buf * BUFB;
        bf16* Bb = Bs + buf * BUFB;
        #pragma unroll
        for (int kk = 0; kk < BKB; kk += 16) {
            FragA a0, a1; FragB bf[4];
            wmma::load_matrix_sync(a0, &Ab[(wm * 32)      * LDAB + kk], LDAB);
            wmma::load_matrix_sync(a1, &Ab[(wm * 32 + 16) * LDAB + kk], LDAB);
            #pragma unroll
            for (int j = 0; j < 4; j++)
                wmma::load_matrix_sync(bf[j], &Bb[(wn * 64 + j * 16) * LDAB + kk], LDAB);
            #pragma unroll
            for (int j = 0; j < 4; j++) {
                wmma::mma_sync(c[0][j], a0, bf[j], c[0][j]);
                wmma::mma_sync(c[1][j], a1, bf[j], c[1][j]);
            }
        }
        __syncthreads();
        buf ^= 1;
    }
}

#define FRAG_INIT(c)                                     \
    _Pragma("unroll")                                    \
    for (int i = 0; i < 2; i++)                          \
        _Pragma("unroll")                                \
        for (int j = 0; j < 4; j++) wmma::fill_fragment(c[i][j], 0.f);

#define FRAG_TO_CS(c, Cs, wm, wn)                                                  \
    _Pragma("unroll")                                                              \
    for (int i = 0; i < 2; i++)                                                    \
        _Pragma("unroll")                                                          \
        for (int j = 0; j < 4; j++)                                                \
            wmma::store_matrix_sync(&Cs[(wm * 32 + i * 16) * LDC + wn * 64 + j * 16], \
                                    c[i][j], LDC, wmma::mem_row_major);

// ---------------- fp32 -> bf16 conversion ----------------
#define N_WIH (G4 * 1024)
#define N_WHH (G4 * HH)
#define N_WOUT (VV * HH)
#define N_EMB (VV * HH)
#define N_GIMG (BB * HH)
#define N_CVT2 ((N_WIH + N_WHH + N_WOUT + N_EMB + N_GIMG) / 2)

__global__ __launch_bounds__(256) void k_cvt(const float* __restrict__ Wih,
                                             const float* __restrict__ Whh,
                                             const float* __restrict__ Wout,
                                             const float* __restrict__ emb,
                                             const float* __restrict__ gimg) {
    long long i2 = (long long)blockIdx.x * 256 + threadIdx.x;
    if (i2 >= N_CVT2) return;
    long long i = i2 * 2;
    const float* src; bf16* dst; long long off;
    if (i < N_WIH)                       { src = Wih;  dst = g_Wih_bf;  off = i; }
    else if (i < (long long)N_WIH + N_WHH) { src = Whh;  dst = g_Whh_bf;  off = i - N_WIH; }
    else if (i < (long long)N_WIH + N_WHH + N_WOUT)
                                         { src = Wout; dst = g_Wout_bf; off = i - N_WIH - N_WHH; }
    else if (i < (long long)N_WIH + N_WHH + N_WOUT + N_EMB)
                                         { src = emb;  dst = g_emb_bf;  off = i - N_WIH - N_WHH - N_WOUT; }
    else                                 { src = gimg; dst = g_gimg_bf; off = i - N_WIH - N_WHH - N_WOUT - N_EMB; }
    float2 v = *(const float2*)(src + off);
    __nv_bfloat162 o = __floats2bfloat162_rn(v.x, v.y);
    *(__nv_bfloat162*)(dst + off) = o;
}

// ---------------- prep: sort + targets + packed row map ----------------
__global__ void k_prep(const int* __restrict__ w, const int* __restrict__ cap,
                       float* __restrict__ out, long long out_size) {
    __shared__ int lens[BB];
    __shared__ int off[TT + 1];
    int i = threadIdx.x;
    lens[i] = cap[i];
    __syncthreads();
    int li = lens[i];
    int rank = 0;
    #pragma unroll 8
    for (int j = 0; j < BB; j++) {
        int lj = lens[j];
        rank += (lj > li) || (lj == li && j < i);
    }
    g_order[rank]  = i;
    g_declen[rank] = li - 1;
    __syncthreads();

    if (i < TT) {
        int c = 0;
        for (int j = 0; j < BB; j++) c += (g_declen[j] > i);
        g_cnt[i] = c;
    }
    __syncthreads();
    if (i == 0) {
        int s = 0;
        for (int t = 0; t < TT; t++) { off[t] = s; s += g_cnt[t]; }
        off[TT] = s;
        g_ntot = s;
    }
    __syncthreads();
    // packed row map (t-major)
    for (int t = 0; t < TT; t++) {
        int c = g_cnt[t];
        for (int b = i; b < c; b += 256) g_rowmap[off[t] + b] = t * 256 + b;
    }
    for (int r = off[TT] + i; r < NROWS; r += 256) g_rowmap[r] = 0;

    long long PRED = (long long)BB * ML * VV;
    if (out_size >= PRED + (long long)BB * TT + BB) {
        int src = g_order[i];
        for (int k = 0; k < TT; k++)
            out[PRED + (long long)i * TT + k] = (float)w[src * ML + k + 1];
        out[PRED + (long long)BB * TT + i] = (float)g_declen[i];
    }
}

__global__ void k_init() {
    int i = blockIdx.x * blockDim.x + threadIdx.x;
    if (i < BB * HH) {
        g_hbuf_bf[0][i] = __float2bfloat16(0.f);
        g_hbuf_bf[1][i] = __float2bfloat16(0.f);
        g_cc[i] = 0.f;
    }
    if (i < NROWS) g_rowsum[i] = 0.f;
    if (i == 0) { g_barcnt = 0; g_barflag = 0; }
}

// ---- image projection: gp[b][n] = gimg[order[b]] . W_ih[n][0:512] ----
__global__ __launch_bounds__(256, 2) void k_gproj() {
    extern __shared__ bf16 dsm[];
    int tid = threadIdx.x;
    int m0 = blockIdx.y * 128, n0 = blockIdx.x * 128;
    int srow = tid >> 1;
    int wp = tid >> 5, wm = wp & 3, wn = wp >> 2;
    const bf16* arow = g_gimg_bf + (size_t)g_order[m0 + srow] * HH;
    const bf16* brow = g_Wih_bf + (size_t)(n0 + srow) * 1024;
    FragC c[2][4];
    FRAG_INIT(c);
    gemm_bf16(arow, brow, dsm, dsm + 2 * BUFB, c, tid);
    #pragma unroll
    for (int i = 0; i < 2; i++)
        #pragma unroll
        for (int j = 0; j < 4; j++)
            wmma::store_matrix_sync(g_gp + (size_t)(m0 + wm * 32 + i * 16) * G4
                                         + n0 + wn * 64 + j * 16,
                                    c[i][j], G4, wmma::mem_row_major);
}

// ---- packed embedding projection + fold ----
__global__ __launch_bounds__(256, 2) void k_xproj(const int* __restrict__ w,
                                                  const float* __restrict__ bih,
                                                  const float* __restrict__ bhh) {
    extern __shared__ bf16 dsm[];
    int tid = threadIdx.x;
    int m0 = blockIdx.y * 128;
    int ntot = g_ntot;
    if (m0 >= ntot) return;
    int n0 = blockIdx.x * 128;
    int srow = tid >> 1;
    int wp = tid >> 5, wm = wp & 3, wn = wp >> 2;
    int tb = g_rowmap[m0 + srow];
    int t_r = tb >> 8, b_r = tb & 255;
    int word = w[g_order[b_r] * ML + t_r];
    const bf16* arow = g_emb_bf + (size_t)word * HH;
    const bf16* brow = g_Wih_bf + (size_t)(n0 + srow) * 1024 + 512;
    FragC c[2][4];
    FRAG_INIT(c);
    gemm_bf16(arow, brow, dsm, dsm + 2 * BUFB, c, tid);
    float* Cs = (float*)dsm;
    FRAG_TO_CS(c, Cs, wm, wn);
    __syncthreads();
    int row = tid >> 1, cb = (tid & 1) * 64;
    int r = m0 + row;
    if (r < ntot) {
        int tb2 = g_rowmap[r];
        int b = tb2 & 255;
        size_t xb = (size_t)tb2 * G4;
        #pragma unroll
        for (int q = 0; q < 16; q++) {
            int n = n0 + cb + q * 4;
            float4 cv = *(const float4*)&Cs[row * LDC + cb + q * 4];
            float4 gp = *(const float4*)(g_gp + (size_t)b * G4 + n);
            float4 b1 = *(const float4*)(bih + n);
            float4 b2 = *(const float4*)(bhh + n);
            float4 v;
            v.x = cv.x + gp.x + b1.x + b2.x;
            v.y = cv.y + gp.y + b1.y + b2.y;
            v.z = cv.z + gp.z + b1.z + b2.z;
            v.w = cv.w + gp.w + b1.w + b2.w;
            *(float4*)(g_xp + xb + n) = v;
        }
    }
}

// ---- persistent recurrent kernel: 64 blocks, C tile 128b x 64 (4 gates x 16 h)
__global__ __launch_bounds__(256) void k_steps() {
    extern __shared__ bf16 dsm[];
    bf16* As = dsm;                    // 2 x BUFB
    bf16* Bs = dsm + 2 * BUFB;         // 2 x BUFB2
    float* Cs = (float*)dsm;           // reuse (128 x LDC2 floats = 34816 B)
    int tid = threadIdx.x;
    int h0 = blockIdx.x * 16;          // 32 h-tiles of 16
    int b0 = blockIdx.y * 128;         // 2 b-tiles
    int wp = tid >> 5, wm = wp & 3, wn = wp >> 2;
    int srowA = tid >> 1, scA = (tid & 1) * 32;
    int srowB = tid >> 2, scB = (tid & 3) * 16;
    int gate = srowB >> 4, hh_s = srowB & 15;
    const bf16* browg = g_Whh_bf + (size_t)(gate * 512 + h0 + hh_s) * HH + scB;
    bf16* asd = As + srowA * LDAB + scA;
    bf16* bsd = Bs + srowB * LDAB + scB;

    for (int t = 0; t < TT; t++) {
        int cnt = g_cnt[t];
        if (b0 < cnt) {
            FragC c[2][2];
            #pragma unroll
            for (int i = 0; i < 2; i++)
                #pragma unroll
                for (int j = 0; j < 2; j++) wmma::fill_fragment(c[i][j], 0.f);
            const bf16* arowg = g_hbuf_bf[t & 1] + (size_t)(b0 + srowA) * HH + scA;
            // prologue
            #pragma unroll
            for (int q = 0; q < 32; q += 8) cp16(asd + q, arowg + q);
            #pragma unroll
            for (int q = 0; q < 16; q += 8) cp16(bsd + q, browg + q);
            asm volatile("cp.async.commit_group;");
            int buf = 0;
            #pragma unroll 1
            for (int k0 = 0; k0 < HH; k0 += BKB) {
                if (k0 + BKB < HH) {
                    int nb = buf ^ 1;
                    #pragma unroll
                    for (int q = 0; q < 32; q += 8)
                        cp16(asd + nb * BUFB + q, arowg + k0 + BKB + q);
                    #pragma unroll
                    for (int q = 0; q < 16; q += 8)
                        cp16(bsd + nb * BUFB2 + q, browg + k0 + BKB + q);
                    asm volatile("cp.async.commit_group;");
                    asm volatile("cp.async.wait_group 1;" ::: "memory");
                } else {
                    asm volatile("cp.async.wait_group 0;" ::: "memory");
                }
                __syncthreads();
                bf16* Ab = As + buf * BUFB;
                bf16* Bb = Bs + buf * BUFB2;
                #pragma unroll
                for (int kk = 0; kk < BKB; kk += 16) {
                    FragA a0, a1; FragB bf0, bf1;
                    wmma::load_matrix_sync(a0, &Ab[(wm * 32)      * LDAB + kk], LDAB);
                    wmma::load_matrix_sync(a1, &Ab[(wm * 32 + 16) * LDAB + kk], LDAB);
                    wmma::load_matrix_sync(bf0, &Bb[(wn * 32)      * LDAB + kk], LDAB);
                    wmma::load_matrix_sync(bf1, &Bb[(wn * 32 + 16) * LDAB + kk], LDAB);
                    wmma::mma_sync(c[0][0], a0, bf0, c[0][0]);
                    wmma::mma_sync(c[0][1], a0, bf1, c[0][1]);
                    wmma::mma_sync(c[1][0], a1, bf0, c[1][0]);
                    wmma::mma_sync(c[1][1], a1, bf1, c[1][1]);
                }
                __syncthreads();
                buf ^= 1;
            }
            #pragma unroll
            for (int i = 0; i < 2; i++)
                #pragma unroll
                for (int j = 0; j < 2; j++)
                    wmma::store_matrix_sync(&Cs[(wm * 32 + i * 16) * LDC2 + wn * 32 + j * 16],
                                            c[i][j], LDC2, wmma::mem_row_major);
            __syncthreads();
            // LSTM elementwise: 128 b x 16 h (C cols: i=hh, f=16+hh, g=32+hh, o=48+hh)
            #pragma unroll
            for (int it = 0; it < 8; it++) {
                int p = it * 256 + tid;        // 0..2047
                int row = p >> 4;
                int hh = p & 15;
                int b = b0 + row;
                if (b >= cnt) continue;
                size_t xpb = (size_t)(t * BB + b) * G4 + h0 + hh;
                float iv = Cs[row * LDC2 + 0  + hh] + g_xp[xpb];
                float fv = Cs[row * LDC2 + 16 + hh] + g_xp[xpb + 512];
                float gv = Cs[row * LDC2 + 32 + hh] + g_xp[xpb + 1024];
                float ov = Cs[row * LDC2 + 48 + hh] + g_xp[xpb + 1536];
                iv = 1.f / (1.f + __expf(-iv));
                fv = 1.f / (1.f + __expf(-fv));
                ov = 1.f / (1.f + __expf(-ov));
                gv = tanhf(gv);
                int hidx = b * HH + h0 + hh;
                float cn = fv * g_cc[hidx] + iv * gv;
                float hn = ov * tanhf(cn);
                g_cc[hidx] = cn;
                bf16 hb = __float2bfloat16(hn);
                g_hbuf_bf[(t + 1) & 1][hidx] = hb;
                g_hall_bf[(size_t)(t * BB + b) * HH + h0 + hh] = hb;
            }
            __syncthreads();
        }
        // grid barrier (64 co-resident blocks) with backoff
        __threadfence();
        if (tid == 0) {
            int v = atomicAdd(&g_barcnt, 1);
            if (v == NBLK - 1) {
                atomicExch(&g_barcnt, 0);
                __threadfence();
                atomicExch(&g_barflag, t + 1);
            } else {
                while (atomicAdd(&g_barflag, 0) < t + 1) { __nanosleep(64); }
                __threadfence();
            }
        }
        __syncthreads();
    }
}

// ---- packed vocab projection: logits -> out + rowsum of exp ----
__global__ __launch_bounds__(256, 2) void k_out1(const float* __restrict__ bout,
                                                 float* __restrict__ out) {
    extern __shared__ bf16 dsm[];
    int tid = threadIdx.x;
    int m0 = blockIdx.y * 128;
    int ntot = g_ntot;
    if (m0 >= ntot) return;
    int n0 = blockIdx.x * 128;
    int srow = tid >> 1;
    int wp = tid >> 5, wm = wp & 3, wn = wp >> 2;
    int tb = g_rowmap[m0 + srow];
    const bf16* arow = g_hall_bf + (size_t)tb * HH;
    int nb = n0 + srow;
    const bf16* brow = g_Wout_bf + (size_t)(nb < VV ? nb : VV - 1) * HH;
    FragC c[2][4];
    FRAG_INIT(c);
    gemm_bf16(arow, brow, dsm, dsm + 2 * BUFB, c, tid);
    float* Cs = (float*)dsm;
    FRAG_TO_CS(c, Cs, wm, wn);
    __syncthreads();

    int row = tid >> 1, cb = (tid & 1) * 64;
    int r = m0 + row;
    if (r < ntot) {
        int tb2 = g_rowmap[r];
        int t = tb2 >> 8, b = tb2 & 255;
        size_t obase = ((size_t)b * ML + t) * VV;
        float psum = 0.f;
        #pragma unroll
        for (int q = 0; q < 16; q++) {
            int n = n0 + cb + q * 4;
            if (n < VV) {
                float4 cv = *(const float4*)&Cs[row * LDC + cb + q * 4];
                float4 bo = *(const float4*)(bout + n);
                float4 v;
                v.x = cv.x + bo.x; v.y = cv.y + bo.y;
                v.z = cv.z + bo.z; v.w = cv.w + bo.w;
                *(float4*)(out + obase + n) = v;
                psum += __expf(v.x) + __expf(v.y) + __expf(v.z) + __expf(v.w);
            }
        }
        atomicAdd(&g_rowsum[tb2], psum);
    }
}

// ---- final: full-output pass; zeros inactive/pad, log-softmax for active ----
__global__ __launch_bounds__(256) void k_out2(float* __restrict__ out) {
    long long idx = (long long)blockIdx.x * 256 + threadIdx.x;
    const int perRow = VV / 4;
    const long long TOT = (long long)BB * ML * perRow;
    if (idx >= TOT) return;
    int r = (int)(idx / perRow);               // r = b*31 + t
    int v4 = (int)(idx % perRow);
    int b = r / ML, t = r - b * ML;
    size_t p = (size_t)r * VV + v4 * 4;
    bool active = (t < TT) && (b < g_cnt[t]);
    float4 o = make_float4(0.f, 0.f, 0.f, 0.f);
    if (active) {
        float ls = logf(g_rowsum[t * BB + b]);
        float4 lv = *(const float4*)(out + p);
        o.x = lv.x - ls; o.y = lv.y - ls; o.z = lv.z - ls; o.w = lv.w - ls;
    }
    *(float4*)(out + p) = o;
}

// ---------------- launch ----------------
extern "C" void kernel_launch(void* const* d_in, const int* in_sizes, int n_in,
                              void* d_out, int out_size) {
    const float* gimg = (const float*)d_in[0];
    const int*   w    = (const int*)d_in[1];
    const int*   cap  = (const int*)d_in[2];
    const float* emb  = (const float*)d_in[3];
    const float* Wih  = (const float*)d_in[4];
    const float* Whh  = (const float*)d_in[5];
    const float* bih  = (const float*)d_in[6];
    const float* bhh  = (const float*)d_in[7];
    const float* Wout = (const float*)d_in[8];
    const float* bout = (const float*)d_in[9];
    float* out = (float*)d_out;

    static int attr_done = 0;
    if (!attr_done) {
        cudaFuncSetAttribute(k_gproj, cudaFuncAttributeMaxDynamicSharedMemorySize, DSMEM_BYTES);
        cudaFuncSetAttribute(k_xproj, cudaFuncAttributeMaxDynamicSharedMemorySize, DSMEM_BYTES);
        cudaFuncSetAttribute(k_steps, cudaFuncAttributeMaxDynamicSharedMemorySize, DSMEM_STEPS);
        cudaFuncSetAttribute(k_out1,  cudaFuncAttributeMaxDynamicSharedMemorySize, DSMEM_BYTES);
        attr_done = 1;
    }

    k_cvt<<<(int)((N_CVT2 + 255) / 256), 256>>>(Wih, Whh, Wout, emb, gimg);
    k_prep<<<1, 256>>>(w, cap, out, (long long)out_size);
    k_init<<<512, 256>>>();
    k_gproj<<<dim3(16, 2), 256, DSMEM_BYTES>>>();
    k_xproj<<<dim3(16, 60), 256, DSMEM_BYTES>>>(w, bih, bhh);
    k_steps<<<dim3(32, 2), 256, DSMEM_STEPS>>>();
    k_out1<<<dim3(79, 60), 256, DSMEM_BYTES>>>(bout, out);
    long long tot = (long long)BB * ML * (VV / 4);
    k_out2<<<(int)((tot + 255) / 256), 256>>>(out);
}